// round 12
// baseline (speedup 1.0000x reference)
#include <cuda_runtime.h>
#include <cuda_fp16.h>
#include <mma.h>
#include <math.h>

using namespace nvcuda;

#define DIMV       512
#define HEADS      8
#define DIM_KEY    32
#define NUM_KEYS   256
#define TOPK       16
#define TOKENS     1024
#define FULLMASK   0xffffffffu

// scratch (device globals; no allocs)
__device__ __align__(16) float  g_q   [TOKENS * DIMV];
__device__ __align__(16) __half g_qh  [TOKENS * DIMV];
__device__ __align__(16) float  g_sim [HEADS * TOKENS * NUM_KEYS];
__device__ __align__(16) __half g_wdTh[DIMV * NUM_KEYS];
__device__ __align__(16) __half g_wupH[NUM_KEYS * DIMV];
__device__ __align__(16) float  g_D   [TOKENS * NUM_KEYS];
__device__ __align__(16) __half g_Sh  [TOKENS * NUM_KEYS];

// ---------------------------------------------------------------------------
// helpers
// ---------------------------------------------------------------------------
__device__ __forceinline__ uint4 pack8h(float4 f0, float4 f1) {
    __half2 h0 = __floats2half2_rn(f0.x, f0.y);
    __half2 h1 = __floats2half2_rn(f0.z, f0.w);
    __half2 h2 = __floats2half2_rn(f1.x, f1.y);
    __half2 h3 = __floats2half2_rn(f1.z, f1.w);
    uint4 u;
    u.x = *reinterpret_cast<unsigned*>(&h0);
    u.y = *reinterpret_cast<unsigned*>(&h1);
    u.z = *reinterpret_cast<unsigned*>(&h2);
    u.w = *reinterpret_cast<unsigned*>(&h3);
    return u;
}

__device__ __forceinline__ void split8(const float* p, uint4& hi, uint4& lo) {
    float4 f0 = *reinterpret_cast<const float4*>(p);
    float4 f1 = *reinterpret_cast<const float4*>(p + 4);
    float v[8] = {f0.x, f0.y, f0.z, f0.w, f1.x, f1.y, f1.z, f1.w};
    __align__(16) __half h[8];
    __align__(16) __half l[8];
#pragma unroll
    for (int i = 0; i < 8; i++) {
        h[i] = __float2half_rn(v[i]);
        l[i] = __float2half_rn(v[i] - __half2float(h[i]));
    }
    hi = *reinterpret_cast<uint4*>(h);
    lo = *reinterpret_cast<uint4*>(l);
}

// ---------------------------------------------------------------------------
// Single-shot HMMA GEMM, K=256 (for K4): A (64x256) + B (256x64) staged in
// smem with ONE barrier, then 32 MMA/warp with no further syncs.
// smem: As[64][264] (33792B) + Bs[256][72] (36864B) = 70656B (dynamic)
// ---------------------------------------------------------------------------
#define SS_SMEM_BYTES (64*264*2 + 256*72*2)

template<int LDA, int NTOT>
__device__ __forceinline__ void hgemm_ss(
    const __half* __restrict__ A, const __half* __restrict__ B,
    float* __restrict__ C, int m0, int n0, char* dsmem)
{
    __half (*As)[264] = (__half(*)[264])dsmem;
    __half (*Bs)[72]  = (__half(*)[72])(dsmem + 64 * 264 * 2);

    const int tid = threadIdx.x;
    const int w = tid >> 5;
    const int wm = w >> 1;
    const int wn = w & 1;

#pragma unroll
    for (int i = 0; i < 8; i++) {
        int u = tid + i * 256;
        int row = u >> 5;
        int c8 = (u & 31) * 8;
        *reinterpret_cast<uint4*>(&As[row][c8]) =
            *reinterpret_cast<const uint4*>(A + (size_t)(m0 + row) * LDA + c8);
    }
#pragma unroll
    for (int i = 0; i < 8; i++) {
        int u = tid + i * 256;
        int row = u >> 3;
        int c8 = (u & 7) * 8;
        *reinterpret_cast<uint4*>(&Bs[row][c8]) =
            *reinterpret_cast<const uint4*>(B + (size_t)row * NTOT + n0 + c8);
    }
    __syncthreads();

    wmma::fragment<wmma::accumulator, 16, 16, 16, float> acc[2];
    wmma::fill_fragment(acc[0], 0.0f);
    wmma::fill_fragment(acc[1], 0.0f);

    wmma::fragment<wmma::matrix_a, 16, 16, 16, __half, wmma::row_major> af;
    wmma::fragment<wmma::matrix_b, 16, 16, 16, __half, wmma::row_major> bf;
#pragma unroll
    for (int ks = 0; ks < 16; ks++) {
        wmma::load_matrix_sync(af, &As[wm * 16][ks * 16], 264);
#pragma unroll
        for (int i = 0; i < 2; i++) {
            wmma::load_matrix_sync(bf, &Bs[ks * 16][wn * 32 + i * 16], 72);
            wmma::mma_sync(acc[i], af, bf, acc[i]);
        }
    }

#pragma unroll
    for (int i = 0; i < 2; i++) {
        wmma::store_matrix_sync(
            &C[(size_t)(m0 + wm * 16) * NTOT + n0 + wn * 32 + i * 16],
            acc[i], NTOT, wmma::mem_row_major);
    }
}

// ---------------------------------------------------------------------------
// fp16 WMMA GEMM, double-buffered BK=32 (for G2, K=512): 64x64 tile.
// smem: As[2][64][40] (10240B) + Bs[2][32][72] (9216B)
// ---------------------------------------------------------------------------
#define HGEMM_SMEM_BYTES (2*64*40*2 + 2*32*72*2)

template<int K, int NTOT>
__device__ __forceinline__ void hgemm_db(
    const __half* __restrict__ Av, const __half* __restrict__ Bv,
    float* __restrict__ C, int m0, int n0, char* smem_raw)
{
    typedef __half AsT[64][40];
    typedef __half BsT[32][72];
    AsT* As = (AsT*)smem_raw;
    BsT* Bs = (BsT*)(smem_raw + 2 * 64 * 40 * 2);

    const int tid = threadIdx.x;
    const int w = tid >> 5;
    const int wm = w >> 1;
    const int wn = w & 1;

    const int arow = tid >> 2;
    const int akq  = (tid & 3) * 8;
    const int brow = tid >> 3;
    const int bnq  = (tid & 7) * 8;

    wmma::fragment<wmma::accumulator, 16, 16, 16, float> acc[2];
    wmma::fill_fragment(acc[0], 0.0f);
    wmma::fill_fragment(acc[1], 0.0f);

    uint4 areg = *reinterpret_cast<const uint4*>(
        Av + (size_t)(m0 + arow) * K + akq);
    uint4 breg = *reinterpret_cast<const uint4*>(
        Bv + (size_t)brow * NTOT + n0 + bnq);

    int buf = 0;
    const int NT = K / 32;
#pragma unroll 1
    for (int kt = 0; kt < NT; kt++) {
        *reinterpret_cast<uint4*>(&As[buf][arow][akq]) = areg;
        *reinterpret_cast<uint4*>(&Bs[buf][brow][bnq]) = breg;
        __syncthreads();

        if (kt + 1 < NT) {
            int k0 = (kt + 1) * 32;
            areg = *reinterpret_cast<const uint4*>(
                Av + (size_t)(m0 + arow) * K + k0 + akq);
            breg = *reinterpret_cast<const uint4*>(
                Bv + (size_t)(k0 + brow) * NTOT + n0 + bnq);
        }

        wmma::fragment<wmma::matrix_a, 16, 16, 16, __half, wmma::row_major> af;
        wmma::fragment<wmma::matrix_b, 16, 16, 16, __half, wmma::row_major> bf;
#pragma unroll
        for (int ks = 0; ks < 2; ks++) {
            wmma::load_matrix_sync(af, &As[buf][wm * 16][ks * 16], 40);
#pragma unroll
            for (int i = 0; i < 2; i++) {
                wmma::load_matrix_sync(bf, &Bs[buf][ks * 16][wn * 32 + i * 16], 72);
                wmma::mma_sync(acc[i], af, bf, acc[i]);
            }
        }
        buf ^= 1;
    }

#pragma unroll
    for (int i = 0; i < 2; i++) {
        wmma::store_matrix_sync(
            &C[(size_t)(m0 + wm * 16) * NTOT + n0 + wn * 32 + i * 16],
            acc[i], NTOT, wmma::mem_row_major);
    }
}

// ---------------------------------------------------------------------------
// G1: split fp16 GEMM (xh*wh + xh*wl + xl*wh), 64x64 tile, BK=32, dbl-buffered
// ---------------------------------------------------------------------------
#define K1_SMEM_BYTES (10240 + 10240 + 9216 + 9216)

__device__ __forceinline__ void g1_split_gemm(
    const float* __restrict__ x, const float* __restrict__ wq,
    int m0, int n0, char* smem_raw)
{
    typedef __half A_t[64][40];
    typedef __half B_t[32][72];
    A_t* Ah = (A_t*)smem_raw;
    A_t* Al = (A_t*)(smem_raw + 10240);
    B_t* Bh = (B_t*)(smem_raw + 20480);
    B_t* Bl = (B_t*)(smem_raw + 29696);

    const int tid = threadIdx.x;
    const int w = tid >> 5;
    const int wm = w >> 1;
    const int wn = w & 1;

    const int arow = tid >> 2;
    const int akq  = (tid & 3) * 8;
    const int brow = tid >> 3;
    const int bnq  = (tid & 7) * 8;

    wmma::fragment<wmma::accumulator, 16, 16, 16, float> acc[2];
    wmma::fill_fragment(acc[0], 0.0f);
    wmma::fill_fragment(acc[1], 0.0f);

    uint4 ah, al, bh, bl;
    split8(&x [(size_t)(m0 + arow) * DIMV + akq], ah, al);
    split8(&wq[(size_t)brow * DIMV + n0 + bnq], bh, bl);

    int buf = 0;
    const int NT = DIMV / 32;
#pragma unroll 1
    for (int kt = 0; kt < NT; kt++) {
        *reinterpret_cast<uint4*>(&Ah[buf][arow][akq]) = ah;
        *reinterpret_cast<uint4*>(&Al[buf][arow][akq]) = al;
        *reinterpret_cast<uint4*>(&Bh[buf][brow][bnq]) = bh;
        *reinterpret_cast<uint4*>(&Bl[buf][brow][bnq]) = bl;
        __syncthreads();

        if (kt + 1 < NT) {
            int k0 = (kt + 1) * 32;
            split8(&x [(size_t)(m0 + arow) * DIMV + k0 + akq], ah, al);
            split8(&wq[(size_t)(k0 + brow) * DIMV + n0 + bnq], bh, bl);
        }

        wmma::fragment<wmma::matrix_a, 16, 16, 16, __half, wmma::row_major> afh, afl;
        wmma::fragment<wmma::matrix_b, 16, 16, 16, __half, wmma::row_major> bfh, bfl;
#pragma unroll
        for (int ks = 0; ks < 2; ks++) {
            wmma::load_matrix_sync(afh, &Ah[buf][wm * 16][ks * 16], 40);
            wmma::load_matrix_sync(afl, &Al[buf][wm * 16][ks * 16], 40);
#pragma unroll
            for (int i = 0; i < 2; i++) {
                wmma::load_matrix_sync(bfh, &Bh[buf][ks * 16][wn * 32 + i * 16], 72);
                wmma::load_matrix_sync(bfl, &Bl[buf][ks * 16][wn * 32 + i * 16], 72);
                wmma::mma_sync(acc[i], afh, bfh, acc[i]);
                wmma::mma_sync(acc[i], afh, bfl, acc[i]);
                wmma::mma_sync(acc[i], afl, bfh, acc[i]);
            }
        }
        buf ^= 1;
    }

    __syncthreads();
    float (*Cs)[68] = (float(*)[68])smem_raw;
#pragma unroll
    for (int i = 0; i < 2; i++)
        wmma::store_matrix_sync(&Cs[wm * 16][wn * 32 + i * 16], acc[i], 68,
                                wmma::mem_row_major);
    __syncthreads();

    const float scale = 0.99999500003749981f;
    int trow = tid >> 2;
    int tc0  = (tid & 3) * 16;
    float4 fo[4];
#pragma unroll
    for (int j = 0; j < 4; j++) {
        float4 f = *reinterpret_cast<const float4*>(&Cs[trow][tc0 + j * 4]);
        f.x *= scale; f.y *= scale; f.z *= scale; f.w *= scale;
        fo[j] = f;
        *reinterpret_cast<float4*>(
            &g_q[(size_t)(m0 + trow) * DIMV + n0 + tc0 + j * 4]) = f;
    }
    uint4 hq0 = pack8h(fo[0], fo[1]);
    uint4 hq1 = pack8h(fo[2], fo[3]);
    __half* qh = &g_qh[(size_t)(m0 + trow) * DIMV + n0 + tc0];
    *reinterpret_cast<uint4*>(qh)     = hq0;
    *reinterpret_cast<uint4*>(qh + 8) = hq1;
}

// ---------------------------------------------------------------------------
// K1: 0..127 G1; 128..255 transpose wdown->half; 256..383 convert wup->half.
// ---------------------------------------------------------------------------
__global__ void __launch_bounds__(256)
k1_fused(const float* __restrict__ x, const float* __restrict__ wq,
         const float* __restrict__ wdown, const float* __restrict__ wup)
{
    __shared__ __align__(16) char smem[K1_SMEM_BYTES];
    int bid = blockIdx.x;
    if (bid < 128) {
        int mb = bid >> 3, nb = bid & 7;
        g1_split_gemm(x, wq, mb * 64, nb * 64, smem);
    } else if (bid < 256) {
        int b = bid - 128;
        int d0 = (b & 15) * 32;
        int e0 = (b >> 4) * 32;
        float (*t)[33] = (float(*)[33])smem;
        int tx = threadIdx.x & 31, ty = threadIdx.x >> 5;
#pragma unroll
        for (int i = 0; i < 4; i++)
            t[ty + i * 8][tx] = wdown[(size_t)(e0 + ty + i * 8) * DIMV + d0 + tx];
        __syncthreads();
#pragma unroll
        for (int i = 0; i < 4; i++)
            g_wdTh[(size_t)(d0 + ty + i * 8) * NUM_KEYS + e0 + tx] =
                __float2half_rn(t[tx][ty + i * 8]);
    } else {
        int idx = (bid - 256) * 1024 + threadIdx.x * 4;
        float4 f = *reinterpret_cast<const float4*>(wup + idx);
        __half2 h0 = __floats2half2_rn(f.x, f.y);
        __half2 h1 = __floats2half2_rn(f.z, f.w);
        uint2 u;
        u.x = *reinterpret_cast<unsigned*>(&h0);
        u.y = *reinterpret_cast<unsigned*>(&h1);
        *reinterpret_cast<uint2*>(&g_wupH[idx]) = u;
    }
}

// ---------------------------------------------------------------------------
// K2 (static smem): 0..63 G2 (D = qh @ wdTh, hgemm_db K=512); 64..191 sim.
// ---------------------------------------------------------------------------
#define SIM_SMEM_BYTES (DIM_KEY*NUM_KEYS*4 + DIM_KEY*64*4)
#define K2_SMEM (SIM_SMEM_BYTES > HGEMM_SMEM_BYTES ? SIM_SMEM_BYTES : HGEMM_SMEM_BYTES)

__global__ void __launch_bounds__(256)
k2_fused(const float* __restrict__ keys)
{
    __shared__ __align__(16) char smem[K2_SMEM];
    int bid = blockIdx.x;
    int tid = threadIdx.x;

    if (bid < 64) {
        int mb = bid >> 2, nb = bid & 3;
        hgemm_db<DIMV, NUM_KEYS>(g_qh, g_wdTh, g_D, mb * 64, nb * 64, smem);
        return;
    }

    // sim: 128 blocks, (64 tokens x 256 keys) per head
    int b = bid - 64;
    int t0 = (b & 15) * 64;
    int h = b >> 4;

    float (*Ks)[NUM_KEYS] = (float(*)[NUM_KEYS])smem;
    float (*Qs)[64] = (float(*)[64])(smem + DIM_KEY * NUM_KEYS * 4);

    {
        const float4* kp = reinterpret_cast<const float4*>(
            keys + (size_t)((h * NUM_KEYS + tid) * 2) * DIM_KEY);
#pragma unroll
        for (int i = 0; i < 8; i++) {
            float4 f = kp[i];
            Ks[4 * i + 0][tid] = f.x;
            Ks[4 * i + 1][tid] = f.y;
            Ks[4 * i + 2][tid] = f.z;
            Ks[4 * i + 3][tid] = f.w;
        }
    }
    {
        int tl = tid & 63;
        int d0 = (tid >> 6) * 8;
        size_t off = (size_t)(t0 + tl) * DIMV + h * DIM_KEY + d0;
        float4 f0 = *reinterpret_cast<const float4*>(g_q + off);
        float4 f1 = *reinterpret_cast<const float4*>(g_q + off + 4);
        Qs[d0 + 0][tl] = f0.x; Qs[d0 + 1][tl] = f0.y;
        Qs[d0 + 2][tl] = f0.z; Qs[d0 + 3][tl] = f0.w;
        Qs[d0 + 4][tl] = f1.x; Qs[d0 + 5][tl] = f1.y;
        Qs[d0 + 6][tl] = f1.z; Qs[d0 + 7][tl] = f1.w;
    }
    __syncthreads();

    int kg = tid & 15;
    int tg = tid >> 4;
    float acc[4][16];
#pragma unroll
    for (int i = 0; i < 4; i++)
#pragma unroll
        for (int j = 0; j < 16; j++) acc[i][j] = 0.0f;

#pragma unroll
    for (int d = 0; d < DIM_KEY; d++) {
        float4 qv = *reinterpret_cast<const float4*>(&Qs[d][tg * 4]);
        float q4[4] = {qv.x, qv.y, qv.z, qv.w};
        float kv[16];
#pragma unroll
        for (int jj = 0; jj < 4; jj++) {
            float4 kk = *reinterpret_cast<const float4*>(&Ks[d][kg * 16 + jj * 4]);
            kv[jj * 4 + 0] = kk.x; kv[jj * 4 + 1] = kk.y;
            kv[jj * 4 + 2] = kk.z; kv[jj * 4 + 3] = kk.w;
        }
#pragma unroll
        for (int i = 0; i < 4; i++)
#pragma unroll
            for (int j = 0; j < 16; j++) acc[i][j] += q4[i] * kv[j];
    }

#pragma unroll
    for (int i = 0; i < 4; i++) {
        int t = t0 + tg * 4 + i;
        float* op = g_sim + ((size_t)h * TOKENS + t) * NUM_KEYS + kg * 16;
#pragma unroll
        for (int jj = 0; jj < 4; jj++) {
            float4 f;
            f.x = acc[i][jj * 4 + 0]; f.y = acc[i][jj * 4 + 1];
            f.z = acc[i][jj * 4 + 2]; f.w = acc[i][jj * 4 + 3];
            *reinterpret_cast<float4*>(op + jj * 4) = f;
        }
    }
}

// ---------------------------------------------------------------------------
// K3: selection with structural fast path.
// ---------------------------------------------------------------------------
__device__ __forceinline__ float gelu_tanh(float x) {
    float x3 = x * x * x;
    float t = tanhf(0.7978845608028654f * (x + 0.044715f * x3));
    return 0.5f * x * (1.0f + t);
}

__device__ __forceinline__ void warp_top16(float* val, int lane,
                                           float* out_v, int* out_i)
{
#pragma unroll
    for (int r = 0; r < TOPK; r++) {
        float bv = val[0]; int bs = 0;
#pragma unroll
        for (int s = 1; s < 8; s++)
            if (val[s] > bv) { bv = val[s]; bs = s; }
        int bp = lane + (bs << 5);
#pragma unroll
        for (int off = 16; off > 0; off >>= 1) {
            float ov = __shfl_xor_sync(FULLMASK, bv, off);
            int   op = __shfl_xor_sync(FULLMASK, bp, off);
            if (ov > bv || (ov == bv && op < bp)) { bv = ov; bp = op; }
        }
        out_v[r] = bv;
        out_i[r] = bp;
        if ((bp & 31) == lane) {
            int ws = bp >> 5;
#pragma unroll
            for (int s = 0; s < 8; s++)
                if (s == ws) val[s] = -INFINITY;
        }
    }
}

__global__ void __launch_bounds__(256) select_kernel()
{
    int t = blockIdx.x;
    int tid = threadIdx.x;
    int w = tid >> 5;
    int lane = tid & 31;

    __shared__ float sS[NUM_KEYS];
    __shared__ float v0s[HEADS][TOPK];
    __shared__ float i0s[HEADS][TOPK];

    sS[tid] = 0.0f;
    __syncthreads();

    float val[8];
    {
        const float* simrow = g_sim + ((size_t)w * TOKENS + t) * NUM_KEYS;
#pragma unroll
        for (int s = 0; s < 8; s++)
            val[s] = simrow[lane + (s << 5)];
    }

    float v0[TOPK]; int i0[TOPK];
    warp_top16(val, lane, v0, i0);

    int imax = -1, i2nd = -1, jst = 0;
#pragma unroll
    for (int j = 0; j < TOPK; j++) {
        int v = i0[j];
        if (v > imax) { i2nd = imax; imax = v; jst = j; }
        else if (v > i2nd) i2nd = v;
    }
    float spread = v0[0] - v0[TOPK - 1];
    bool fast = (float)(imax - i2nd) > spread;

    if (fast) {
        float myv = -INFINITY;
#pragma unroll
        for (int r = 0; r < TOPK; r++)
            if (lane == r) myv = v0[r];
        float mye = expf(myv - v0[0]);
        float esum = mye;
#pragma unroll
        for (int off = 16; off > 0; off >>= 1)
            esum += __shfl_xor_sync(FULLMASK, esum, off);
        if (lane < TOPK) {
            int pk = lane * TOPK + jst;
            float dv = g_D[(size_t)t * NUM_KEYS + pk];
            float g = gelu_tanh(dv) * (mye / esum);
            atomicAdd(&sS[pk], g);
        }
    } else {
        if (lane == 0) {
#pragma unroll
            for (int r = 0; r < TOPK; r++) {
                v0s[w][r] = v0[r];
                i0s[w][r] = (float)i0[r];
            }
        }
        __syncwarp();
        float val2[8];
#pragma unroll
        for (int s = 0; s < 8; s++) {
            int p = lane + (s << 5);
            val2[s] = v0s[w][p >> 4] + i0s[w][p & 15];
        }
        float scf[TOPK]; int pk[TOPK];
        warp_top16(val2, lane, scf, pk);

        float myscf = -INFINITY; int mypk = 0;
#pragma unroll
        for (int r = 0; r < TOPK; r++)
            if (lane == r) { myscf = scf[r]; mypk = pk[r]; }
        float m = scf[0];
#pragma unroll
        for (int r = 1; r < TOPK; r++) m = fmaxf(m, scf[r]);
        float mye = expf(myscf - m);
        float esum = mye;
#pragma unroll
        for (int off = 16; off > 0; off >>= 1)
            esum += __shfl_xor_sync(FULLMASK, esum, off);
        if (lane < TOPK) {
            float dv = g_D[(size_t)t * NUM_KEYS + mypk];
            float g = gelu_tanh(dv) * (mye / esum);
            atomicAdd(&sS[mypk], g);
        }
    }
    __syncthreads();

    g_Sh[(size_t)t * NUM_KEYS + tid] = __float2half_rn(sS[tid]);
}

// ---------------------------------------------------------------------------
// K4: out = Sh @ wupH  (single-shot HMMA, dynamic smem)
// ---------------------------------------------------------------------------
__global__ void __launch_bounds__(256)
k4_gemm(float* __restrict__ out)
{
    extern __shared__ __align__(16) char dsmem[];
    int bid = blockIdx.x;
    int mb = bid >> 3, nb = bid & 7;
    hgemm_ss<NUM_KEYS, DIMV>(g_Sh, g_wupH, out, mb * 64, nb * 64, dsmem);
}

// ---------------------------------------------------------------------------
extern "C" void kernel_launch(void* const* d_in, const int* in_sizes, int n_in,
                              void* d_out, int out_size)
{
    const float* x     = (const float*)d_in[0];
    const float* w_q   = (const float*)d_in[1];
    const float* keys  = (const float*)d_in[2];
    const float* wdown = (const float*)d_in[3];
    const float* wup   = (const float*)d_in[4];
    float* out = (float*)d_out;

    cudaFuncSetAttribute(k4_gemm,
        cudaFuncAttributeMaxDynamicSharedMemorySize, SS_SMEM_BYTES);

    k1_fused<<<384, 256>>>(x, w_q, wdown, wup);
    k2_fused<<<192, 256>>>(keys);
    select_kernel<<<TOKENS, 256>>>();
    k4_gemm<<<128, 256, SS_SMEM_BYTES>>>(out);
}

// round 13
// speedup vs baseline: 1.0739x; 1.0739x over previous
#include <cuda_runtime.h>
#include <cuda_fp16.h>
#include <mma.h>
#include <math.h>

using namespace nvcuda;

#define DIMV       512
#define HEADS      8
#define DIM_KEY    32
#define NUM_KEYS   256
#define QCOLS      256
#define TOPK       16
#define TOKENS     1024
#define FULLMASK   0xffffffffu

// scratch (device globals; no allocs)
__device__ __align__(16) float  g_q   [TOKENS * QCOLS];    // exact q, cols 0..255
__device__ __align__(16) __half g_qh  [TOKENS * DIMV];     // fp16 q, all cols
__device__ __align__(16) float  g_sim [HEADS * TOKENS * NUM_KEYS];
__device__ __align__(16) __half g_wdTh[DIMV * NUM_KEYS];
__device__ __align__(16) __half g_wupH[NUM_KEYS * DIMV];
__device__ __align__(16) float  g_D   [TOKENS * NUM_KEYS];
__device__ __align__(16) __half g_Sh  [TOKENS * NUM_KEYS];

// ---------------------------------------------------------------------------
// helpers
// ---------------------------------------------------------------------------
__device__ __forceinline__ uint4 pack8h(float4 f0, float4 f1) {
    __half2 h0 = __floats2half2_rn(f0.x, f0.y);
    __half2 h1 = __floats2half2_rn(f0.z, f0.w);
    __half2 h2 = __floats2half2_rn(f1.x, f1.y);
    __half2 h3 = __floats2half2_rn(f1.z, f1.w);
    uint4 u;
    u.x = *reinterpret_cast<unsigned*>(&h0);
    u.y = *reinterpret_cast<unsigned*>(&h1);
    u.z = *reinterpret_cast<unsigned*>(&h2);
    u.w = *reinterpret_cast<unsigned*>(&h3);
    return u;
}

__device__ __forceinline__ void split8(const float* p, uint4& hi, uint4& lo) {
    float4 f0 = *reinterpret_cast<const float4*>(p);
    float4 f1 = *reinterpret_cast<const float4*>(p + 4);
    float v[8] = {f0.x, f0.y, f0.z, f0.w, f1.x, f1.y, f1.z, f1.w};
    __align__(16) __half h[8];
    __align__(16) __half l[8];
#pragma unroll
    for (int i = 0; i < 8; i++) {
        h[i] = __float2half_rn(v[i]);
        l[i] = __float2half_rn(v[i] - __half2float(h[i]));
    }
    hi = *reinterpret_cast<uint4*>(h);
    lo = *reinterpret_cast<uint4*>(l);
}

// ---------------------------------------------------------------------------
// Single-shot HMMA GEMM, K=256 (K4): one barrier, then 32 MMA/warp.
// smem: As[64][264] + Bs[256][72] = 70656B (dynamic)
// ---------------------------------------------------------------------------
#define SS_SMEM_BYTES (64*264*2 + 256*72*2)

template<int LDA, int NTOT>
__device__ __forceinline__ void hgemm_ss(
    const __half* __restrict__ A, const __half* __restrict__ B,
    float* __restrict__ C, int m0, int n0, char* dsmem)
{
    __half (*As)[264] = (__half(*)[264])dsmem;
    __half (*Bs)[72]  = (__half(*)[72])(dsmem + 64 * 264 * 2);

    const int tid = threadIdx.x;
    const int w = tid >> 5;
    const int wm = w >> 1;
    const int wn = w & 1;

#pragma unroll
    for (int i = 0; i < 8; i++) {
        int u = tid + i * 256;
        int row = u >> 5;
        int c8 = (u & 31) * 8;
        *reinterpret_cast<uint4*>(&As[row][c8]) =
            *reinterpret_cast<const uint4*>(A + (size_t)(m0 + row) * LDA + c8);
    }
#pragma unroll
    for (int i = 0; i < 8; i++) {
        int u = tid + i * 256;
        int row = u >> 3;
        int c8 = (u & 7) * 8;
        *reinterpret_cast<uint4*>(&Bs[row][c8]) =
            *reinterpret_cast<const uint4*>(B + (size_t)row * NTOT + n0 + c8);
    }
    __syncthreads();

    wmma::fragment<wmma::accumulator, 16, 16, 16, float> acc[2];
    wmma::fill_fragment(acc[0], 0.0f);
    wmma::fill_fragment(acc[1], 0.0f);

    wmma::fragment<wmma::matrix_a, 16, 16, 16, __half, wmma::row_major> af;
    wmma::fragment<wmma::matrix_b, 16, 16, 16, __half, wmma::row_major> bf;
#pragma unroll
    for (int ks = 0; ks < 16; ks++) {
        wmma::load_matrix_sync(af, &As[wm * 16][ks * 16], 264);
#pragma unroll
        for (int i = 0; i < 2; i++) {
            wmma::load_matrix_sync(bf, &Bs[ks * 16][wn * 32 + i * 16], 72);
            wmma::mma_sync(acc[i], af, bf, acc[i]);
        }
    }

#pragma unroll
    for (int i = 0; i < 2; i++) {
        wmma::store_matrix_sync(
            &C[(size_t)(m0 + wm * 16) * NTOT + n0 + wn * 32 + i * 16],
            acc[i], NTOT, wmma::mem_row_major);
    }
}

// ---------------------------------------------------------------------------
// fp16 WMMA GEMM, double-buffered BK=32 (G2, K=512): 64x64 tile, half inputs.
// smem: As[2][64][40] + Bs[2][32][72] = 19456B
// ---------------------------------------------------------------------------
#define HGEMM_SMEM_BYTES (2*64*40*2 + 2*32*72*2)

template<int K, int NTOT>
__device__ __forceinline__ void hgemm_db(
    const __half* __restrict__ Av, const __half* __restrict__ Bv,
    float* __restrict__ C, int m0, int n0, char* smem_raw)
{
    typedef __half AsT[64][40];
    typedef __half BsT[32][72];
    AsT* As = (AsT*)smem_raw;
    BsT* Bs = (BsT*)(smem_raw + 2 * 64 * 40 * 2);

    const int tid = threadIdx.x;
    const int w = tid >> 5;
    const int wm = w >> 1;
    const int wn = w & 1;

    const int arow = tid >> 2;
    const int akq  = (tid & 3) * 8;
    const int brow = tid >> 3;
    const int bnq  = (tid & 7) * 8;

    wmma::fragment<wmma::accumulator, 16, 16, 16, float> acc[2];
    wmma::fill_fragment(acc[0], 0.0f);
    wmma::fill_fragment(acc[1], 0.0f);

    uint4 areg = *reinterpret_cast<const uint4*>(
        Av + (size_t)(m0 + arow) * K + akq);
    uint4 breg = *reinterpret_cast<const uint4*>(
        Bv + (size_t)brow * NTOT + n0 + bnq);

    int buf = 0;
    const int NT = K / 32;
#pragma unroll 1
    for (int kt = 0; kt < NT; kt++) {
        *reinterpret_cast<uint4*>(&As[buf][arow][akq]) = areg;
        *reinterpret_cast<uint4*>(&Bs[buf][brow][bnq]) = breg;
        __syncthreads();

        if (kt + 1 < NT) {
            int k0 = (kt + 1) * 32;
            areg = *reinterpret_cast<const uint4*>(
                Av + (size_t)(m0 + arow) * K + k0 + akq);
            breg = *reinterpret_cast<const uint4*>(
                Bv + (size_t)(k0 + brow) * NTOT + n0 + bnq);
        }

        wmma::fragment<wmma::matrix_a, 16, 16, 16, __half, wmma::row_major> af;
        wmma::fragment<wmma::matrix_b, 16, 16, 16, __half, wmma::row_major> bf;
#pragma unroll
        for (int ks = 0; ks < 2; ks++) {
            wmma::load_matrix_sync(af, &As[buf][wm * 16][ks * 16], 40);
#pragma unroll
            for (int i = 0; i < 2; i++) {
                wmma::load_matrix_sync(bf, &Bs[buf][ks * 16][wn * 32 + i * 16], 72);
                wmma::mma_sync(acc[i], af, bf, acc[i]);
            }
        }
        buf ^= 1;
    }

#pragma unroll
    for (int i = 0; i < 2; i++) {
        wmma::store_matrix_sync(
            &C[(size_t)(m0 + wm * 16) * NTOT + n0 + wn * 32 + i * 16],
            acc[i], NTOT, wmma::mem_row_major);
    }
}

// ---------------------------------------------------------------------------
// G1a: split fp16 GEMM (xh*wh + xh*wl + xl*wh) for q cols 0..255.
// Writes fp32 g_q (stride QCOLS) + fp16 g_qh (stride DIMV).
// ---------------------------------------------------------------------------
#define K1_SMEM_BYTES (10240 + 10240 + 9216 + 9216)

__device__ __forceinline__ void g1_split_gemm(
    const float* __restrict__ x, const float* __restrict__ wq,
    int m0, int n0, char* smem_raw)
{
    typedef __half A_t[64][40];
    typedef __half B_t[32][72];
    A_t* Ah = (A_t*)smem_raw;
    A_t* Al = (A_t*)(smem_raw + 10240);
    B_t* Bh = (B_t*)(smem_raw + 20480);
    B_t* Bl = (B_t*)(smem_raw + 29696);

    const int tid = threadIdx.x;
    const int w = tid >> 5;
    const int wm = w >> 1;
    const int wn = w & 1;

    const int arow = tid >> 2;
    const int akq  = (tid & 3) * 8;
    const int brow = tid >> 3;
    const int bnq  = (tid & 7) * 8;

    wmma::fragment<wmma::accumulator, 16, 16, 16, float> acc[2];
    wmma::fill_fragment(acc[0], 0.0f);
    wmma::fill_fragment(acc[1], 0.0f);

    uint4 ah, al, bh, bl;
    split8(&x [(size_t)(m0 + arow) * DIMV + akq], ah, al);
    split8(&wq[(size_t)brow * DIMV + n0 + bnq], bh, bl);

    int buf = 0;
    const int NT = DIMV / 32;
#pragma unroll 1
    for (int kt = 0; kt < NT; kt++) {
        *reinterpret_cast<uint4*>(&Ah[buf][arow][akq]) = ah;
        *reinterpret_cast<uint4*>(&Al[buf][arow][akq]) = al;
        *reinterpret_cast<uint4*>(&Bh[buf][brow][bnq]) = bh;
        *reinterpret_cast<uint4*>(&Bl[buf][brow][bnq]) = bl;
        __syncthreads();

        if (kt + 1 < NT) {
            int k0 = (kt + 1) * 32;
            split8(&x [(size_t)(m0 + arow) * DIMV + k0 + akq], ah, al);
            split8(&wq[(size_t)(k0 + brow) * DIMV + n0 + bnq], bh, bl);
        }

        wmma::fragment<wmma::matrix_a, 16, 16, 16, __half, wmma::row_major> afh, afl;
        wmma::fragment<wmma::matrix_b, 16, 16, 16, __half, wmma::row_major> bfh, bfl;
#pragma unroll
        for (int ks = 0; ks < 2; ks++) {
            wmma::load_matrix_sync(afh, &Ah[buf][wm * 16][ks * 16], 40);
            wmma::load_matrix_sync(afl, &Al[buf][wm * 16][ks * 16], 40);
#pragma unroll
            for (int i = 0; i < 2; i++) {
                wmma::load_matrix_sync(bfh, &Bh[buf][ks * 16][wn * 32 + i * 16], 72);
                wmma::load_matrix_sync(bfl, &Bl[buf][ks * 16][wn * 32 + i * 16], 72);
                wmma::mma_sync(acc[i], afh, bfh, acc[i]);
                wmma::mma_sync(acc[i], afh, bfl, acc[i]);
                wmma::mma_sync(acc[i], afl, bfh, acc[i]);
            }
        }
        buf ^= 1;
    }

    __syncthreads();
    float (*Cs)[68] = (float(*)[68])smem_raw;
#pragma unroll
    for (int i = 0; i < 2; i++)
        wmma::store_matrix_sync(&Cs[wm * 16][wn * 32 + i * 16], acc[i], 68,
                                wmma::mem_row_major);
    __syncthreads();

    const float scale = 0.99999500003749981f;
    int trow = tid >> 2;
    int tc0  = (tid & 3) * 16;
    float4 fo[4];
#pragma unroll
    for (int j = 0; j < 4; j++) {
        float4 f = *reinterpret_cast<const float4*>(&Cs[trow][tc0 + j * 4]);
        f.x *= scale; f.y *= scale; f.z *= scale; f.w *= scale;
        fo[j] = f;
        *reinterpret_cast<float4*>(
            &g_q[(size_t)(m0 + trow) * QCOLS + n0 + tc0 + j * 4]) = f;
    }
    uint4 hq0 = pack8h(fo[0], fo[1]);
    uint4 hq1 = pack8h(fo[2], fo[3]);
    __half* qh = &g_qh[(size_t)(m0 + trow) * DIMV + n0 + tc0];
    *reinterpret_cast<uint4*>(qh)     = hq0;
    *reinterpret_cast<uint4*>(qh + 8) = hq1;
}

// ---------------------------------------------------------------------------
// G1b: plain fp16 GEMM for q cols 256..511 (value path only) -> g_qh.
// fp32 inputs converted inline; BK=32 double-buffered.
// ---------------------------------------------------------------------------
__device__ __forceinline__ void g1_plain_gemm(
    const float* __restrict__ x, const float* __restrict__ wq,
    int m0, int n0, char* smem_raw)   // n0 in [256, 512)
{
    typedef __half AsT[64][40];
    typedef __half BsT[32][72];
    AsT* As = (AsT*)smem_raw;
    BsT* Bs = (BsT*)(smem_raw + 2 * 64 * 40 * 2);

    const int tid = threadIdx.x;
    const int w = tid >> 5;
    const int wm = w >> 1;
    const int wn = w & 1;

    const int arow = tid >> 2;
    const int akq  = (tid & 3) * 8;
    const int brow = tid >> 3;
    const int bnq  = (tid & 7) * 8;

    wmma::fragment<wmma::accumulator, 16, 16, 16, float> acc[2];
    wmma::fill_fragment(acc[0], 0.0f);
    wmma::fill_fragment(acc[1], 0.0f);

    uint4 areg, breg;
    {
        const float* a = &x[(size_t)(m0 + arow) * DIMV + akq];
        areg = pack8h(*reinterpret_cast<const float4*>(a),
                      *reinterpret_cast<const float4*>(a + 4));
        const float* b = &wq[(size_t)brow * DIMV + n0 + bnq];
        breg = pack8h(*reinterpret_cast<const float4*>(b),
                      *reinterpret_cast<const float4*>(b + 4));
    }

    int buf = 0;
    const int NT = DIMV / 32;
#pragma unroll 1
    for (int kt = 0; kt < NT; kt++) {
        *reinterpret_cast<uint4*>(&As[buf][arow][akq]) = areg;
        *reinterpret_cast<uint4*>(&Bs[buf][brow][bnq]) = breg;
        __syncthreads();

        if (kt + 1 < NT) {
            int k0 = (kt + 1) * 32;
            const float* a = &x[(size_t)(m0 + arow) * DIMV + k0 + akq];
            areg = pack8h(*reinterpret_cast<const float4*>(a),
                          *reinterpret_cast<const float4*>(a + 4));
            const float* b = &wq[(size_t)(k0 + brow) * DIMV + n0 + bnq];
            breg = pack8h(*reinterpret_cast<const float4*>(b),
                          *reinterpret_cast<const float4*>(b + 4));
        }

        wmma::fragment<wmma::matrix_a, 16, 16, 16, __half, wmma::row_major> af;
        wmma::fragment<wmma::matrix_b, 16, 16, 16, __half, wmma::row_major> bf;
#pragma unroll
        for (int ks = 0; ks < 2; ks++) {
            wmma::load_matrix_sync(af, &As[buf][wm * 16][ks * 16], 40);
#pragma unroll
            for (int i = 0; i < 2; i++) {
                wmma::load_matrix_sync(bf, &Bs[buf][ks * 16][wn * 32 + i * 16], 72);
                wmma::mma_sync(acc[i], af, bf, acc[i]);
            }
        }
        buf ^= 1;
    }

    // epilogue: scale, convert to half, write g_qh only
    __syncthreads();
    float (*Cs)[68] = (float(*)[68])smem_raw;
#pragma unroll
    for (int i = 0; i < 2; i++)
        wmma::store_matrix_sync(&Cs[wm * 16][wn * 32 + i * 16], acc[i], 68,
                                wmma::mem_row_major);
    __syncthreads();

    const float scale = 0.99999500003749981f;
    int trow = tid >> 2;
    int tc0  = (tid & 3) * 16;
    float4 fo[4];
#pragma unroll
    for (int j = 0; j < 4; j++) {
        float4 f = *reinterpret_cast<const float4*>(&Cs[trow][tc0 + j * 4]);
        f.x *= scale; f.y *= scale; f.z *= scale; f.w *= scale;
        fo[j] = f;
    }
    uint4 hq0 = pack8h(fo[0], fo[1]);
    uint4 hq1 = pack8h(fo[2], fo[3]);
    __half* qh = &g_qh[(size_t)(m0 + trow) * DIMV + n0 + tc0];
    *reinterpret_cast<uint4*>(qh)     = hq0;
    *reinterpret_cast<uint4*>(qh + 8) = hq1;
}

// ---------------------------------------------------------------------------
// K1: 0..63 split GEMM (cols 0-255); 64..127 plain GEMM (cols 256-511);
//     128..255 transpose wdown->half; 256..383 convert wup->half.
// ---------------------------------------------------------------------------
__global__ void __launch_bounds__(256)
k1_fused(const float* __restrict__ x, const float* __restrict__ wq,
         const float* __restrict__ wdown, const float* __restrict__ wup)
{
    __shared__ __align__(16) char smem[K1_SMEM_BYTES];
    int bid = blockIdx.x;
    if (bid < 64) {
        int mb = bid >> 2, nb = bid & 3;
        g1_split_gemm(x, wq, mb * 64, nb * 64, smem);
    } else if (bid < 128) {
        int b = bid - 64;
        int mb = b >> 2, nb = b & 3;
        g1_plain_gemm(x, wq, mb * 64, 256 + nb * 64, smem);
    } else if (bid < 256) {
        int b = bid - 128;
        int d0 = (b & 15) * 32;
        int e0 = (b >> 4) * 32;
        float (*t)[33] = (float(*)[33])smem;
        int tx = threadIdx.x & 31, ty = threadIdx.x >> 5;
#pragma unroll
        for (int i = 0; i < 4; i++)
            t[ty + i * 8][tx] = wdown[(size_t)(e0 + ty + i * 8) * DIMV + d0 + tx];
        __syncthreads();
#pragma unroll
        for (int i = 0; i < 4; i++)
            g_wdTh[(size_t)(d0 + ty + i * 8) * NUM_KEYS + e0 + tx] =
                __float2half_rn(t[tx][ty + i * 8]);
    } else {
        int idx = (bid - 256) * 1024 + threadIdx.x * 4;
        float4 f = *reinterpret_cast<const float4*>(wup + idx);
        __half2 h0 = __floats2half2_rn(f.x, f.y);
        __half2 h1 = __floats2half2_rn(f.z, f.w);
        uint2 u;
        u.x = *reinterpret_cast<unsigned*>(&h0);
        u.y = *reinterpret_cast<unsigned*>(&h1);
        *reinterpret_cast<uint2*>(&g_wupH[idx]) = u;
    }
}

// ---------------------------------------------------------------------------
// K2: 0..63 G2 (D = qh @ wdTh, hgemm_db K=512); 64..191 sim (fp32).
// ---------------------------------------------------------------------------
#define SIM_SMEM_BYTES (DIM_KEY*NUM_KEYS*4 + DIM_KEY*64*4)
#define K2_SMEM (SIM_SMEM_BYTES > HGEMM_SMEM_BYTES ? SIM_SMEM_BYTES : HGEMM_SMEM_BYTES)

__global__ void __launch_bounds__(256)
k2_fused(const float* __restrict__ keys)
{
    __shared__ __align__(16) char smem[K2_SMEM];
    int bid = blockIdx.x;
    int tid = threadIdx.x;

    if (bid < 64) {
        int mb = bid >> 2, nb = bid & 3;
        hgemm_db<DIMV, NUM_KEYS>(g_qh, g_wdTh, g_D, mb * 64, nb * 64, smem);
        return;
    }

    // sim: 128 blocks, (64 tokens x 256 keys) per head
    int b = bid - 64;
    int t0 = (b & 15) * 64;
    int h = b >> 4;

    float (*Ks)[NUM_KEYS] = (float(*)[NUM_KEYS])smem;
    float (*Qs)[64] = (float(*)[64])(smem + DIM_KEY * NUM_KEYS * 4);

    {
        const float4* kp = reinterpret_cast<const float4*>(
            keys + (size_t)((h * NUM_KEYS + tid) * 2) * DIM_KEY);
#pragma unroll
        for (int i = 0; i < 8; i++) {
            float4 f = kp[i];
            Ks[4 * i + 0][tid] = f.x;
            Ks[4 * i + 1][tid] = f.y;
            Ks[4 * i + 2][tid] = f.z;
            Ks[4 * i + 3][tid] = f.w;
        }
    }
    {
        int tl = tid & 63;
        int d0 = (tid >> 6) * 8;
        size_t off = (size_t)(t0 + tl) * QCOLS + h * DIM_KEY + d0;
        float4 f0 = *reinterpret_cast<const float4*>(g_q + off);
        float4 f1 = *reinterpret_cast<const float4*>(g_q + off + 4);
        Qs[d0 + 0][tl] = f0.x; Qs[d0 + 1][tl] = f0.y;
        Qs[d0 + 2][tl] = f0.z; Qs[d0 + 3][tl] = f0.w;
        Qs[d0 + 4][tl] = f1.x; Qs[d0 + 5][tl] = f1.y;
        Qs[d0 + 6][tl] = f1.z; Qs[d0 + 7][tl] = f1.w;
    }
    __syncthreads();

    int kg = tid & 15;
    int tg = tid >> 4;
    float acc[4][16];
#pragma unroll
    for (int i = 0; i < 4; i++)
#pragma unroll
        for (int j = 0; j < 16; j++) acc[i][j] = 0.0f;

#pragma unroll
    for (int d = 0; d < DIM_KEY; d++) {
        float4 qv = *reinterpret_cast<const float4*>(&Qs[d][tg * 4]);
        float q4[4] = {qv.x, qv.y, qv.z, qv.w};
        float kv[16];
#pragma unroll
        for (int jj = 0; jj < 4; jj++) {
            float4 kk = *reinterpret_cast<const float4*>(&Ks[d][kg * 16 + jj * 4]);
            kv[jj * 4 + 0] = kk.x; kv[jj * 4 + 1] = kk.y;
            kv[jj * 4 + 2] = kk.z; kv[jj * 4 + 3] = kk.w;
        }
#pragma unroll
        for (int i = 0; i < 4; i++)
#pragma unroll
            for (int j = 0; j < 16; j++) acc[i][j] += q4[i] * kv[j];
    }

#pragma unroll
    for (int i = 0; i < 4; i++) {
        int t = t0 + tg * 4 + i;
        float* op = g_sim + ((size_t)h * TOKENS + t) * NUM_KEYS + kg * 16;
#pragma unroll
        for (int jj = 0; jj < 4; jj++) {
            float4 f;
            f.x = acc[i][jj * 4 + 0]; f.y = acc[i][jj * 4 + 1];
            f.z = acc[i][jj * 4 + 2]; f.w = acc[i][jj * 4 + 3];
            *reinterpret_cast<float4*>(op + jj * 4) = f;
        }
    }
}

// ---------------------------------------------------------------------------
// K3: selection with structural fast path.
// ---------------------------------------------------------------------------
__device__ __forceinline__ float gelu_tanh(float x) {
    float x3 = x * x * x;
    float t = tanhf(0.7978845608028654f * (x + 0.044715f * x3));
    return 0.5f * x * (1.0f + t);
}

__device__ __forceinline__ void warp_top16(float* val, int lane,
                                           float* out_v, int* out_i)
{
#pragma unroll
    for (int r = 0; r < TOPK; r++) {
        float bv = val[0]; int bs = 0;
#pragma unroll
        for (int s = 1; s < 8; s++)
            if (val[s] > bv) { bv = val[s]; bs = s; }
        int bp = lane + (bs << 5);
#pragma unroll
        for (int off = 16; off > 0; off >>= 1) {
            float ov = __shfl_xor_sync(FULLMASK, bv, off);
            int   op = __shfl_xor_sync(FULLMASK, bp, off);
            if (ov > bv || (ov == bv && op < bp)) { bv = ov; bp = op; }
        }
        out_v[r] = bv;
        out_i[r] = bp;
        if ((bp & 31) == lane) {
            int ws = bp >> 5;
#pragma unroll
            for (int s = 0; s < 8; s++)
                if (s == ws) val[s] = -INFINITY;
        }
    }
}

__global__ void __launch_bounds__(256) select_kernel()
{
    int t = blockIdx.x;
    int tid = threadIdx.x;
    int w = tid >> 5;
    int lane = tid & 31;

    __shared__ float sS[NUM_KEYS];
    __shared__ float v0s[HEADS][TOPK];
    __shared__ float i0s[HEADS][TOPK];

    sS[tid] = 0.0f;
    __syncthreads();

    float val[8];
    {
        const float* simrow = g_sim + ((size_t)w * TOKENS + t) * NUM_KEYS;
#pragma unroll
        for (int s = 0; s < 8; s++)
            val[s] = simrow[lane + (s << 5)];
    }

    float v0[TOPK]; int i0[TOPK];
    warp_top16(val, lane, v0, i0);

    int imax = -1, i2nd = -1, jst = 0;
#pragma unroll
    for (int j = 0; j < TOPK; j++) {
        int v = i0[j];
        if (v > imax) { i2nd = imax; imax = v; jst = j; }
        else if (v > i2nd) i2nd = v;
    }
    float spread = v0[0] - v0[TOPK - 1];
    bool fast = (float)(imax - i2nd) > spread;

    if (fast) {
        float myv = -INFINITY;
#pragma unroll
        for (int r = 0; r < TOPK; r++)
            if (lane == r) myv = v0[r];
        float mye = expf(myv - v0[0]);
        float esum = mye;
#pragma unroll
        for (int off = 16; off > 0; off >>= 1)
            esum += __shfl_xor_sync(FULLMASK, esum, off);
        if (lane < TOPK) {
            int pk = lane * TOPK + jst;
            float dv = g_D[(size_t)t * NUM_KEYS + pk];
            float g = gelu_tanh(dv) * (mye / esum);
            atomicAdd(&sS[pk], g);
        }
    } else {
        if (lane == 0) {
#pragma unroll
            for (int r = 0; r < TOPK; r++) {
                v0s[w][r] = v0[r];
                i0s[w][r] = (float)i0[r];
            }
        }
        __syncwarp();
        float val2[8];
#pragma unroll
        for (int s = 0; s < 8; s++) {
            int p = lane + (s << 5);
            val2[s] = v0s[w][p >> 4] + i0s[w][p & 15];
        }
        float scf[TOPK]; int pk[TOPK];
        warp_top16(val2, lane, scf, pk);

        float myscf = -INFINITY; int mypk = 0;
#pragma unroll
        for (int r = 0; r < TOPK; r++)
            if (lane == r) { myscf = scf[r]; mypk = pk[r]; }
        float m = scf[0];
#pragma unroll
        for (int r = 1; r < TOPK; r++) m = fmaxf(m, scf[r]);
        float mye = expf(myscf - m);
        float esum = mye;
#pragma unroll
        for (int off = 16; off > 0; off >>= 1)
            esum += __shfl_xor_sync(FULLMASK, esum, off);
        if (lane < TOPK) {
            float dv = g_D[(size_t)t * NUM_KEYS + mypk];
            float g = gelu_tanh(dv) * (mye / esum);
            atomicAdd(&sS[mypk], g);
        }
    }
    __syncthreads();

    g_Sh[(size_t)t * NUM_KEYS + tid] = __float2half_rn(sS[tid]);
}

// ---------------------------------------------------------------------------
// K4: out = Sh @ wupH  (single-shot HMMA, dynamic smem)
// ---------------------------------------------------------------------------
__global__ void __launch_bounds__(256)
k4_gemm(float* __restrict__ out)
{
    extern __shared__ __align__(16) char dsmem[];
    int bid = blockIdx.x;
    int mb = bid >> 3, nb = bid & 7;
    hgemm_ss<NUM_KEYS, DIMV>(g_Sh, g_wupH, out, mb * 64, nb * 64, dsmem);
}

// ---------------------------------------------------------------------------
extern "C" void kernel_launch(void* const* d_in, const int* in_sizes, int n_in,
                              void* d_out, int out_size)
{
    const float* x     = (const float*)d_in[0];
    const float* w_q   = (const float*)d_in[1];
    const float* keys  = (const float*)d_in[2];
    const float* wdown = (const float*)d_in[3];
    const float* wup   = (const float*)d_in[4];
    float* out = (float*)d_out;

    cudaFuncSetAttribute(k4_gemm,
        cudaFuncAttributeMaxDynamicSharedMemorySize, SS_SMEM_BYTES);

    k1_fused<<<384, 256>>>(x, w_q, wdown, wup);
    k2_fused<<<192, 256>>>(keys);
    select_kernel<<<TOKENS, 256>>>();
    k4_gemm<<<128, 256, SS_SMEM_BYTES>>>(out);
}